// round 14
// baseline (speedup 1.0000x reference)
#include <cuda_runtime.h>
#include <cuda_fp16.h>
#include <cstdint>

// ---------------------------------------------------------------------------
// Problem constants
// ---------------------------------------------------------------------------
#define N_IMG  16
#define CI     256
#define CO     256
#define HW     56
#define KTAP   13
#define PAD    6
#define HP     68           // 56 + 12
#define WPAD   76           // 56 + 12 padding + slack

#define N_TILES 896

// Scratch (device globals; no cudaMalloc allowed)
__device__ __half g_xp[(size_t)N_IMG * HP * WPAD * CI];     // [n][hp][wp][ci]  ~42 MB
__device__ __half g_wt[(size_t)KTAP * KTAP * CO * CI];      // [tap][co][ci]    ~22 MB
__device__ unsigned int g_ctr;                              // work-steal counter

// ---------------------------------------------------------------------------
// Helpers (arch-neutral PTX: mma.sync / ldmatrix / cp.async)
// ---------------------------------------------------------------------------
__device__ __forceinline__ uint32_t smem_u32(const void* p) {
    uint32_t a;
    asm("{ .reg .u64 t; cvta.to.shared.u64 t, %1; cvt.u32.u64 %0, t; }" : "=r"(a) : "l"(p));
    return a;
}
__device__ __forceinline__ uint32_t swz(uint32_t off) {      // SW128: bits[4:6] ^= bits[7:9]
    return off ^ ((off >> 3) & 0x70);
}
__device__ __forceinline__ void cp16(uint32_t dst, const void* src) {
    asm volatile("cp.async.cg.shared.global [%0], [%1], 16;" :: "r"(dst), "l"(src) : "memory");
}
#define CP_COMMIT() asm volatile("cp.async.commit_group;" ::: "memory")
#define CP_WAIT(n)  asm volatile("cp.async.wait_group %0;" :: "n"(n) : "memory")

__device__ __forceinline__ void ldsm4(uint32_t* r, uint32_t addr) {
    asm volatile("ldmatrix.sync.aligned.m8n8.x4.shared.b16 {%0,%1,%2,%3}, [%4];"
                 : "=r"(r[0]), "=r"(r[1]), "=r"(r[2]), "=r"(r[3]) : "r"(addr));
}
__device__ __forceinline__ void ldsm2(uint32_t* r, uint32_t addr) {
    asm volatile("ldmatrix.sync.aligned.m8n8.x2.shared.b16 {%0,%1}, [%2];"
                 : "=r"(r[0]), "=r"(r[1]) : "r"(addr));
}
__device__ __forceinline__ void mma16816(float* d, const uint32_t* a, const uint32_t* b) {
    asm volatile(
        "mma.sync.aligned.m16n8k16.row.col.f32.f16.f16.f32 "
        "{%0,%1,%2,%3}, {%4,%5,%6,%7}, {%8,%9}, {%0,%1,%2,%3};"
        : "+f"(d[0]), "+f"(d[1]), "+f"(d[2]), "+f"(d[3])
        : "r"(a[0]), "r"(a[1]), "r"(a[2]), "r"(a[3]), "r"(b[0]), "r"(b[1]));
}

// ---------------------------------------------------------------------------
// Fused prepass: pad/transpose input + transpose weights + counter reset
// ---------------------------------------------------------------------------
#define PAD_BLOCKS (N_IMG * HP)          // 1088
#define WT_BLOCKS  (CO * KTAP)           // 3328
#define SROW 57
#define WSROW 258

__global__ void __launch_bounds__(256) prep_kernel(
    const float* __restrict__ x, const float* __restrict__ w)
{
    __shared__ __half s[256 * SROW];
    const int bx  = blockIdx.x;
    const int tid = threadIdx.x;

    if (bx == 0 && tid == 0) g_ctr = 0;      // reset work-steal counter (every replay)

    if (bx < PAD_BLOCKS) {
        const int n  = bx / HP;
        const int hp = bx % HP;
        const int h  = hp - PAD;
        const bool hv = (h >= 0) && (h < HW);
        const int wq = tid & 63, cq = tid >> 6;
        if (hv && wq < HW) {
            const float* xr = x + ((size_t)(n * CI + cq) * HW + h) * HW + wq;
            #pragma unroll 8
            for (int c0 = 0; c0 < CI; c0 += 4)
                s[(c0 + cq) * SROW + wq] = __float2half(xr[(size_t)c0 * HW * HW]);
        }
        __syncthreads();
        const int cp2 = tid & 127;
        const int wo  = tid >> 7;
        __half2* dst = (__half2*)(g_xp + ((size_t)(n * HP + hp) * WPAD) * CI) + cp2;
        const __half* s0 = s + (2 * cp2) * SROW;
        const __half* s1 = s + (2 * cp2 + 1) * SROW;
        #pragma unroll
        for (int k = 0; k < WPAD / 2; ++k) {
            const int wp = wo + 2 * k;
            const int ww = wp - PAD;
            __half2 v = __half2half2(__float2half(0.f));
            if (hv && ww >= 0 && ww < HW) v = __halves2half2(s0[ww], s1[ww]);
            dst[(size_t)wp * (CI / 2)] = v;
        }
    } else {
        const int idx = bx - PAD_BLOCKS;
        const int co = idx / KTAP;
        const int kr = idx - co * KTAP;
        const float* src = w + ((size_t)co * CI) * (KTAP * KTAP) + kr * KTAP;
        #pragma unroll
        for (int k = 0; k < 13; ++k) {
            const int j  = tid + k * 256;
            const int ci = j / 13;
            const int tp = j - ci * 13;
            s[tp * WSROW + ci] = __float2half(src[(size_t)ci * (KTAP * KTAP) + tp]);
        }
        __syncthreads();
        __half* dst = g_wt + (size_t)(kr * KTAP) * (CO * CI) + (size_t)co * CI + tid;
        #pragma unroll
        for (int tp = 0; tp < 13; ++tp)
            dst[(size_t)tp * (CO * CI)] = s[tp * WSROW + tid];
    }
}

// ---------------------------------------------------------------------------
// Main: PERSISTENT implicit-GEMM conv + BN + SiLU via mma.sync
// 456 CTAs (152 SM x 3 resident) pull tiles from g_ctr (LPT order: 704
// full-length tiles first, border tiles 12,12,10,10,8,8 last).
// Per tile: M=128 co x N=112 spatial, warp 64x56, NSTAGE=2, r-skip.
// ---------------------------------------------------------------------------
#define A_BYTES     16384          // 128 rows x 128B
#define B_BYTES     14336          // 112 rows x 128B
#define STAGE_BYTES (A_BYTES + B_BYTES)     // 30720
#define NSTAGE      2
#define SMEM_DYN    (NSTAGE * STAGE_BYTES + 2048)   // stages + bcast slot + align

__global__ void __launch_bounds__(128, 3) conv_main_kernel(
    const float* __restrict__ gamma, const float* __restrict__ beta,
    const float* __restrict__ rmean, const float* __restrict__ rvar,
    float* __restrict__ out)
{
    extern __shared__ char smem_raw[];
    const uint32_t base = (smem_u32(smem_raw) + 1023u) & ~1023u;
    const uint32_t bcast = base + NSTAGE * STAGE_BYTES;     // 4B tile-id slot

    const int tid = threadIdx.x;
    const int l   = tid & 31;
    const int wid = tid >> 5;

    // ---- tile-invariant geometry -----------------------------------------
    const int c16  = tid & 7;
    const int row0 = tid >> 3;
    const uint32_t a_dst0 = swz((uint32_t)(row0 * 128 + c16 * 16));
    const uint32_t b_dst0 = a_dst0 + A_BYTES;
    uint32_t b_off[7];
    #pragma unroll
    for (int i = 0; i < 7; ++i) {
        const int rj = row0 + 16 * i;
        const int jr = (rj >= 56);
        b_off[i] = (uint32_t)(rj + jr * (WPAD - 56)) * (CI * 2);
    }

    const int wm = wid >> 1, wn = wid & 1;
    const int m0 = wm * 64, n0 = wn * 56;
    uint32_t aoff[4], axor[4];
    uint32_t boff[3], bxor[3];
    const uint32_t hi_a = (uint32_t)((l >> 4) << 4);
    const uint32_t hi_b = (uint32_t)(((l >> 3) & 1) << 4);
    #pragma unroll
    for (int mt = 0; mt < 4; ++mt) {
        const int r = m0 + 16 * mt + (l & 15);
        aoff[mt] = (uint32_t)(r * 128);
        axor[mt] = (uint32_t)((r & 7) << 4);
    }
    #pragma unroll
    for (int bt = 0; bt < 3; ++bt) {
        const int r = n0 + 16 * bt + (l & 7) + ((l >> 4) << 3);
        boff[bt] = (uint32_t)(r * 128);
        bxor[bt] = (uint32_t)((r & 7) << 4);
    }
    const int lm = l & 15;
    const int trow = n0 + 48 + (lm & 7);
    const uint32_t toff = (uint32_t)(trow * 128);
    const uint32_t txor = (uint32_t)((trow & 7) << 4);
    const uint32_t thi  = (uint32_t)(((lm >> 3) & 1) << 4);

    // ---- persistent tile loop --------------------------------------------
    for (;;) {
        if (tid == 0) {
            const unsigned int t = atomicAdd(&g_ctr, 1u);
            asm volatile("st.shared.u32 [%0], %1;" :: "r"(bcast), "r"(t) : "memory");
        }
        __syncthreads();            // publish tile id; also orders prior-tile
                                    // smem reads before this tile's overwrites
        unsigned int idx;
        asm volatile("ld.shared.u32 %0, [%1];" : "=r"(idx) : "r"(bcast));
        if (idx >= N_TILES) break;

        // LPT decode: long tiles (ht 3..24) at ids 0..703, border last
        int cob, n, ht;
        if (idx < 704) {
            cob = idx >= 352;
            const int j = (int)idx - cob * 352;
            n  = j / 22;
            ht = 3 + (j - n * 22);
        } else {
            const int k = (int)idx - 704;
            cob = k >= 96;
            const int j = k - cob * 96;
            n = j / 6;
            const int b = j - n * 6;           // 12,12,10,10,8,8 tap-rows
            ht = (b == 0) ? 2 : (b == 1) ? 25 : (b == 2) ? 1
               : (b == 3) ? 26 : (b == 4) ? 0 : 27;
        }
        const int h0 = ht * 2;

        const int r_lo = max(0, PAD - 1 - h0);
        const int r_hi = min(KTAP - 1, HW + PAD - 1 - h0);
        const int NIT  = 4 * KTAP * (r_hi - r_lo + 1);

        const char* a_base = (const char*)g_wt
            + (size_t)(cob * 128 + row0) * (CI * 2) + c16 * 16;
        const char* b_base = (const char*)g_xp
            + (size_t)(n * HP + h0) * WPAD * (CI * 2) + c16 * 16;

        uint32_t p_woff = (uint32_t)(r_lo * KTAP) * (CO * CI * 2);
        uint32_t p_xoff = (uint32_t)r_lo * WPAD * (CI * 2);
        int p_kc = 0, p_s = 0, p_ws = 0;

        auto issue = [&]() {
            const uint32_t sb = base + (uint32_t)p_ws * STAGE_BYTES;
            const char* asrc = a_base + p_woff;
            const char* bsrc = b_base + p_xoff;
            #pragma unroll
            for (int i = 0; i < 8; ++i)
                cp16(sb + a_dst0 + i * 2048u, asrc + (size_t)i * 16 * (CI * 2));
            #pragma unroll
            for (int i = 0; i < 7; ++i)
                cp16(sb + b_dst0 + i * 2048u, bsrc + b_off[i]);
            CP_COMMIT();
            p_ws ^= 1;
            p_woff += 128;
            p_xoff += 128;
            if (++p_kc == 4) {
                p_kc = 0;
                p_woff += (uint32_t)(CO * CI * 2) - 512;
                if (++p_s == KTAP) { p_s = 0; p_xoff += (uint32_t)(WPAD - (KTAP - 1)) * (CI * 2) - 512; }
                else               { p_xoff += (uint32_t)(CI * 2) - 512; }
            }
        };

        float acc[4][7][4];
        #pragma unroll
        for (int i = 0; i < 4; ++i)
            #pragma unroll
            for (int j = 0; j < 7; ++j)
                #pragma unroll
                for (int k = 0; k < 4; ++k) acc[i][j][k] = 0.f;

        auto compute = [&](int stage) {
            const uint32_t ab = base + (uint32_t)stage * STAGE_BYTES;
            const uint32_t bb = ab + A_BYTES;
            #pragma unroll
            for (int kk = 0; kk < 4; ++kk) {
                const uint32_t ka = (uint32_t)kk * 32;
                uint32_t a[4][4], b[3][4], t2[2];
                #pragma unroll
                for (int mt = 0; mt < 4; ++mt)
                    ldsm4(a[mt], ab + aoff[mt] + ((ka + hi_a) ^ axor[mt]));
                #pragma unroll
                for (int bt = 0; bt < 3; ++bt)
                    ldsm4(b[bt], bb + boff[bt] + ((ka + hi_b) ^ bxor[bt]));
                ldsm2(t2, bb + toff + ((ka + thi) ^ txor));
                #pragma unroll
                for (int bt = 0; bt < 3; ++bt) {
                    #pragma unroll
                    for (int mt = 0; mt < 4; ++mt) {
                        mma16816(acc[mt][2 * bt],     a[mt], b[bt]);
                        mma16816(acc[mt][2 * bt + 1], a[mt], b[bt] + 2);
                    }
                }
                #pragma unroll
                for (int mt = 0; mt < 4; ++mt)
                    mma16816(acc[mt][6], a[mt], t2);
            }
        };

        // ---- mainloop: NIT K-stages, 2-stage pipeline, 1 barrier/iter
        issue();                        // group 0 -> stage 0
        int rs = 0;
        #pragma unroll 1
        for (int i = 0; i < NIT - 1; ++i) {
            CP_WAIT(0);
            __syncthreads();
            issue();
            compute(rs);
            rs ^= 1;
        }
        CP_WAIT(0);
        __syncthreads();
        compute(rs);

        // ---- epilogue: BN + SiLU, registers -> NCHW fp32 (float2 stores)
        const int h = h0 + wn;
        #pragma unroll
        for (int mt = 0; mt < 4; ++mt) {
            #pragma unroll
            for (int hf = 0; hf < 2; ++hf) {
                const int co = cob * 128 + m0 + 16 * mt + 8 * hf + (l >> 2);
                const float sc = gamma[co] * rsqrtf(rvar[co] + 1e-5f);
                const float sh = beta[co] - rmean[co] * sc;
                float* op = out + ((size_t)(n * CO + co) * HW + h) * HW + 2 * (l & 3);
                #pragma unroll
                for (int nt = 0; nt < 7; ++nt) {
                    const float y0 = acc[mt][nt][hf * 2 + 0] * sc + sh;
                    const float y1 = acc[mt][nt][hf * 2 + 1] * sc + sh;
                    float2 v;
                    v.x = y0 / (1.f + __expf(-y0));
                    v.y = y1 / (1.f + __expf(-y1));
                    *(float2*)(op + 8 * nt) = v;
                }
            }
        }
    }
}

// ---------------------------------------------------------------------------
// kernel_launch
// ---------------------------------------------------------------------------
extern "C" void kernel_launch(void* const* d_in, const int* in_sizes, int n_in,
                              void* d_out, int out_size)
{
    const float* x     = (const float*)d_in[0];
    const float* w     = (const float*)d_in[1];
    const float* gamma = (const float*)d_in[2];
    const float* beta  = (const float*)d_in[3];
    const float* rmean = (const float*)d_in[4];
    const float* rvar  = (const float*)d_in[5];
    float* out = (float*)d_out;

    cudaFuncSetAttribute(conv_main_kernel,
                         cudaFuncAttributeMaxDynamicSharedMemorySize, SMEM_DYN);

    prep_kernel<<<PAD_BLOCKS + WT_BLOCKS, 256>>>(x, w);
    conv_main_kernel<<<456, 128, SMEM_DYN>>>(gamma, beta, rmean, rvar, out);
}

// round 15
// speedup vs baseline: 1.0092x; 1.0092x over previous
#include <cuda_runtime.h>
#include <cuda_fp16.h>
#include <cstdint>

// ---------------------------------------------------------------------------
// Problem constants
// ---------------------------------------------------------------------------
#define N_IMG  16
#define CI     256
#define CO     256
#define HW     56
#define KTAP   13
#define PAD    6
#define HP     68           // 56 + 12
#define WPAD   76           // 56 + 12 padding + slack

// Scratch (device globals; no cudaMalloc allowed)
__device__ __half g_xp[(size_t)N_IMG * HP * WPAD * CI];     // [n][hp][wp][ci]  ~42 MB
__device__ __half g_wt[(size_t)KTAP * KTAP * CO * CI];      // [tap][co][ci]    ~22 MB

// ---------------------------------------------------------------------------
// Helpers (arch-neutral PTX: mma.sync / ldmatrix / cp.async)
// ---------------------------------------------------------------------------
__device__ __forceinline__ uint32_t smem_u32(const void* p) {
    uint32_t a;
    asm("{ .reg .u64 t; cvta.to.shared.u64 t, %1; cvt.u32.u64 %0, t; }" : "=r"(a) : "l"(p));
    return a;
}
__device__ __forceinline__ uint32_t swz(uint32_t off) {      // SW128: bits[4:6] ^= bits[7:9]
    return off ^ ((off >> 3) & 0x70);
}
__device__ __forceinline__ void cp16(uint32_t dst, const void* src) {
    asm volatile("cp.async.cg.shared.global [%0], [%1], 16;" :: "r"(dst), "l"(src) : "memory");
}
#define CP_COMMIT() asm volatile("cp.async.commit_group;" ::: "memory")
#define CP_WAIT(n)  asm volatile("cp.async.wait_group %0;" :: "n"(n) : "memory")

__device__ __forceinline__ void ldsm4(uint32_t* r, uint32_t addr) {
    asm volatile("ldmatrix.sync.aligned.m8n8.x4.shared.b16 {%0,%1,%2,%3}, [%4];"
                 : "=r"(r[0]), "=r"(r[1]), "=r"(r[2]), "=r"(r[3]) : "r"(addr));
}
__device__ __forceinline__ void ldsm2(uint32_t* r, uint32_t addr) {
    asm volatile("ldmatrix.sync.aligned.m8n8.x2.shared.b16 {%0,%1}, [%2];"
                 : "=r"(r[0]), "=r"(r[1]) : "r"(addr));
}
__device__ __forceinline__ void mma16816(float* d, const uint32_t* a, const uint32_t* b) {
    asm volatile(
        "mma.sync.aligned.m16n8k16.row.col.f32.f16.f16.f32 "
        "{%0,%1,%2,%3}, {%4,%5,%6,%7}, {%8,%9}, {%0,%1,%2,%3};"
        : "+f"(d[0]), "+f"(d[1]), "+f"(d[2]), "+f"(d[3])
        : "r"(a[0]), "r"(a[1]), "r"(a[2]), "r"(a[3]), "r"(b[0]), "r"(b[1]));
}

// ---------------------------------------------------------------------------
// Fused prepass: pad/transpose input + transpose weights (one launch)
// ---------------------------------------------------------------------------
#define PAD_BLOCKS (N_IMG * HP)          // 1088
#define WT_BLOCKS  (CO * KTAP)           // 3328
#define SROW 57
#define WSROW 258

__global__ void __launch_bounds__(256) prep_kernel(
    const float* __restrict__ x, const float* __restrict__ w)
{
    __shared__ __half s[256 * SROW];
    const int bx  = blockIdx.x;
    const int tid = threadIdx.x;

    if (bx < PAD_BLOCKS) {
        const int n  = bx / HP;
        const int hp = bx % HP;
        const int h  = hp - PAD;
        const bool hv = (h >= 0) && (h < HW);
        const int wq = tid & 63, cq = tid >> 6;
        if (hv && wq < HW) {
            const float* xr = x + ((size_t)(n * CI + cq) * HW + h) * HW + wq;
            #pragma unroll 8
            for (int c0 = 0; c0 < CI; c0 += 4)
                s[(c0 + cq) * SROW + wq] = __float2half(xr[(size_t)c0 * HW * HW]);
        }
        __syncthreads();
        const int cp2 = tid & 127;
        const int wo  = tid >> 7;
        __half2* dst = (__half2*)(g_xp + ((size_t)(n * HP + hp) * WPAD) * CI) + cp2;
        const __half* s0 = s + (2 * cp2) * SROW;
        const __half* s1 = s + (2 * cp2 + 1) * SROW;
        #pragma unroll
        for (int k = 0; k < WPAD / 2; ++k) {
            const int wp = wo + 2 * k;
            const int ww = wp - PAD;
            __half2 v = __half2half2(__float2half(0.f));
            if (hv && ww >= 0 && ww < HW) v = __halves2half2(s0[ww], s1[ww]);
            dst[(size_t)wp * (CI / 2)] = v;
        }
    } else {
        const int idx = bx - PAD_BLOCKS;
        const int co = idx / KTAP;
        const int kr = idx - co * KTAP;
        const float* src = w + ((size_t)co * CI) * (KTAP * KTAP) + kr * KTAP;
        #pragma unroll
        for (int k = 0; k < 13; ++k) {
            const int j  = tid + k * 256;
            const int ci = j / 13;
            const int tp = j - ci * 13;
            s[tp * WSROW + ci] = __float2half(src[(size_t)ci * (KTAP * KTAP) + tp]);
        }
        __syncthreads();
        __half* dst = g_wt + (size_t)(kr * KTAP) * (CO * CI) + (size_t)co * CI + tid;
        #pragma unroll
        for (int tp = 0; tp < 13; ++tp)
            dst[(size_t)tp * (CO * CI)] = s[tp * WSROW + tid];
    }
}

// ---------------------------------------------------------------------------
// Main: implicit-GEMM conv + BN + SiLU via mma.sync (m16n8k16 f16->f32)
// CTA: 128 threads (4 warps 2x2), tile M=128 co x N=112 spatial,
// warp tile 64x56.  3 CTAs/SM, NSTAGE=2, regs<=170, r-skip.
// LPT grid ordering: 704 full-length CTAs first, border CTAs
// (12,12,10,10,8,8 tap-rows) last.  grid = 896 (1-D).
// ---------------------------------------------------------------------------
#define A_BYTES     16384          // 128 rows x 128B
#define B_BYTES     14336          // 112 rows x 128B
#define STAGE_BYTES (A_BYTES + B_BYTES)     // 30720
#define NSTAGE      2
#define SMEM_DYN    (NSTAGE * STAGE_BYTES + 1024)   // 62464

__global__ void __launch_bounds__(128, 3) conv_main_kernel(
    const float* __restrict__ gamma, const float* __restrict__ beta,
    const float* __restrict__ rmean, const float* __restrict__ rvar,
    float* __restrict__ out)
{
    extern __shared__ char smem_raw[];
    const uint32_t base = (smem_u32(smem_raw) + 1023u) & ~1023u;

    const int tid = threadIdx.x;
    const int l   = tid & 31;
    const int wid = tid >> 5;

    // ---- LPT decode: long tiles (ht 3..24) at bids 0..703, border last
    const int idx = blockIdx.x;
    int cob, n, ht;
    if (idx < 704) {
        cob = idx >= 352;
        const int j = idx - cob * 352;
        n  = j / 22;
        ht = 3 + (j - n * 22);                 // 13 tap-rows
    } else {
        const int k = idx - 704;
        cob = k >= 96;
        const int j = k - cob * 96;
        n = j / 6;
        const int b = j - n * 6;               // LPT within border: 12,12,10,10,8,8
        ht = (b == 0) ? 2 : (b == 1) ? 25 : (b == 2) ? 1
           : (b == 3) ? 26 : (b == 4) ? 0 : 27;
    }
    const int h0 = ht * 2;

    // ---- r-skip range
    const int r_lo = max(0, PAD - 1 - h0);
    const int r_hi = min(KTAP - 1, HW + PAD - 1 - h0);
    const int NIT  = 4 * KTAP * (r_hi - r_lo + 1);   // always even

    // ---- cp.async geometry: 8x16B per 128B row; 128 thr = 16 rows/pass
    const int c16  = tid & 7;
    const int row0 = tid >> 3;
    const char* a_base = (const char*)g_wt
        + (size_t)(cob * 128 + row0) * (CI * 2) + c16 * 16;
    const uint32_t a_dst0 = swz((uint32_t)(row0 * 128 + c16 * 16));
    const char* b_base = (const char*)g_xp
        + (size_t)(n * HP + h0) * WPAD * (CI * 2) + c16 * 16;
    uint32_t b_off[7];
    #pragma unroll
    for (int i = 0; i < 7; ++i) {
        const int rj = row0 + 16 * i;
        const int jr = (rj >= 56);
        b_off[i] = (uint32_t)(rj + jr * (WPAD - 56)) * (CI * 2);
    }
    const uint32_t b_dst0 = swz((uint32_t)(row0 * 128 + c16 * 16)) + A_BYTES;

    // Producer counters — u32 offsets; start at tap-row r_lo
    uint32_t p_woff = (uint32_t)(r_lo * KTAP) * (CO * CI * 2);
    uint32_t p_xoff = (uint32_t)r_lo * WPAD * (CI * 2);
    int p_kc = 0, p_s = 0, p_ws = 0;

    auto issue = [&]() {
        const uint32_t sb = base + (uint32_t)p_ws * STAGE_BYTES;
        const char* asrc = a_base + p_woff;
        const char* bsrc = b_base + p_xoff;
        #pragma unroll
        for (int i = 0; i < 8; ++i)
            cp16(sb + a_dst0 + i * 2048u, asrc + (size_t)i * 16 * (CI * 2));
        #pragma unroll
        for (int i = 0; i < 7; ++i)
            cp16(sb + b_dst0 + i * 2048u, bsrc + b_off[i]);
        CP_COMMIT();
        p_ws ^= 1;
        p_woff += 128;
        p_xoff += 128;
        if (++p_kc == 4) {
            p_kc = 0;
            p_woff += (uint32_t)(CO * CI * 2) - 512;
            if (++p_s == KTAP) { p_s = 0; p_xoff += (uint32_t)(WPAD - (KTAP - 1)) * (CI * 2) - 512; }
            else               { p_xoff += (uint32_t)(CI * 2) - 512; }
        }
    };

    // ---- MMA fragment geometry (warp grid 2x2, warp tile 64(M) x 56(N))
    const int wm = wid >> 1, wn = wid & 1;
    const int m0 = wm * 64, n0 = wn * 56;
    uint32_t aoff[4], axor[4];
    uint32_t boff[3], bxor[3];
    const uint32_t hi_a = (uint32_t)((l >> 4) << 4);
    const uint32_t hi_b = (uint32_t)(((l >> 3) & 1) << 4);
    #pragma unroll
    for (int mt = 0; mt < 4; ++mt) {
        const int r = m0 + 16 * mt + (l & 15);
        aoff[mt] = (uint32_t)(r * 128);
        axor[mt] = (uint32_t)((r & 7) << 4);
    }
    #pragma unroll
    for (int bt = 0; bt < 3; ++bt) {
        const int r = n0 + 16 * bt + (l & 7) + ((l >> 4) << 3);
        boff[bt] = (uint32_t)(r * 128);
        bxor[bt] = (uint32_t)((r & 7) << 4);
    }
    const int lm = l & 15;
    const int trow = n0 + 48 + (lm & 7);
    const uint32_t toff = (uint32_t)(trow * 128);
    const uint32_t txor = (uint32_t)((trow & 7) << 4);
    const uint32_t thi  = (uint32_t)(((lm >> 3) & 1) << 4);

    float acc[4][7][4];
    #pragma unroll
    for (int i = 0; i < 4; ++i)
        #pragma unroll
        for (int j = 0; j < 7; ++j)
            #pragma unroll
            for (int k = 0; k < 4; ++k) acc[i][j][k] = 0.f;

    auto compute = [&](int stage) {
        const uint32_t ab = base + (uint32_t)stage * STAGE_BYTES;
        const uint32_t bb = ab + A_BYTES;
        #pragma unroll
        for (int kk = 0; kk < 4; ++kk) {
            const uint32_t ka = (uint32_t)kk * 32;
            uint32_t a[4][4], b[3][4], t2[2];
            // interleave A/B issue so the first mma's operands land earliest
            ldsm4(a[0], ab + aoff[0] + ((ka + hi_a) ^ axor[0]));
            ldsm4(b[0], bb + boff[0] + ((ka + hi_b) ^ bxor[0]));
            ldsm4(a[1], ab + aoff[1] + ((ka + hi_a) ^ axor[1]));
            ldsm4(b[1], bb + boff[1] + ((ka + hi_b) ^ bxor[1]));
            ldsm4(a[2], ab + aoff[2] + ((ka + hi_a) ^ axor[2]));
            ldsm4(b[2], bb + boff[2] + ((ka + hi_b) ^ bxor[2]));
            ldsm4(a[3], ab + aoff[3] + ((ka + hi_a) ^ axor[3]));
            ldsm2(t2, bb + toff + ((ka + thi) ^ txor));
            #pragma unroll
            for (int bt = 0; bt < 3; ++bt) {
                #pragma unroll
                for (int mt = 0; mt < 4; ++mt) {
                    mma16816(acc[mt][2 * bt],     a[mt], b[bt]);
                    mma16816(acc[mt][2 * bt + 1], a[mt], b[bt] + 2);
                }
            }
            #pragma unroll
            for (int mt = 0; mt < 4; ++mt)
                mma16816(acc[mt][6], a[mt], t2);
        }
    };

    // ---- mainloop: NIT K-stages, 2-stage pipeline, one barrier per iter.
    issue();                        // group 0 -> stage 0
    int rs = 0;
    #pragma unroll 2
    for (int i = 0; i < NIT - 1; ++i) {
        CP_WAIT(0);                 // group i complete (issued 1 iter earlier)
        __syncthreads();
        issue();                    // group i+1 -> stage (i+1)%2
        compute(rs);
        rs ^= 1;
    }
    CP_WAIT(0);
    __syncthreads();
    compute(rs);                    // last iteration

    // ---- epilogue: BN + SiLU, registers -> NCHW fp32 via float2 stores
    const int h = h0 + wn;
    #pragma unroll
    for (int mt = 0; mt < 4; ++mt) {
        #pragma unroll
        for (int hf = 0; hf < 2; ++hf) {
            const int co = cob * 128 + m0 + 16 * mt + 8 * hf + (l >> 2);
            const float sc = gamma[co] * rsqrtf(rvar[co] + 1e-5f);
            const float sh = beta[co] - rmean[co] * sc;
            float* op = out + ((size_t)(n * CO + co) * HW + h) * HW + 2 * (l & 3);
            #pragma unroll
            for (int nt = 0; nt < 7; ++nt) {
                const float y0 = acc[mt][nt][hf * 2 + 0] * sc + sh;
                const float y1 = acc[mt][nt][hf * 2 + 1] * sc + sh;
                float2 v;
                v.x = y0 / (1.f + __expf(-y0));
                v.y = y1 / (1.f + __expf(-y1));
                *(float2*)(op + 8 * nt) = v;
            }
        }
    }
}

// ---------------------------------------------------------------------------
// kernel_launch
// ---------------------------------------------------------------------------
extern "C" void kernel_launch(void* const* d_in, const int* in_sizes, int n_in,
                              void* d_out, int out_size)
{
    const float* x     = (const float*)d_in[0];
    const float* w     = (const float*)d_in[1];
    const float* gamma = (const float*)d_in[2];
    const float* beta  = (const float*)d_in[3];
    const float* rmean = (const float*)d_in[4];
    const float* rvar  = (const float*)d_in[5];
    float* out = (float*)d_out;

    cudaFuncSetAttribute(conv_main_kernel,
                         cudaFuncAttributeMaxDynamicSharedMemorySize, SMEM_DYN);

    prep_kernel<<<PAD_BLOCKS + WT_BLOCKS, 256>>>(x, w);
    conv_main_kernel<<<896, 128, SMEM_DYN>>>(gamma, beta, rmean, rvar, out);
}

// round 16
// speedup vs baseline: 1.0200x; 1.0107x over previous
#include <cuda_runtime.h>
#include <cuda_fp16.h>
#include <cstdint>

// ---------------------------------------------------------------------------
// Problem constants
// ---------------------------------------------------------------------------
#define N_IMG  16
#define CI     256
#define CO     256
#define HW     56
#define KTAP   13
#define PAD    6
#define HP     68           // 56 + 12
#define WPAD   76           // 56 + 12 padding + slack

// Scratch (device globals; no cudaMalloc allowed).
// NOTE: g_xp is zero-initialized at module load; padding cells are NEVER
// written by any kernel, so they remain exactly 0.0h across all replays.
__device__ __half g_xp[(size_t)N_IMG * HP * WPAD * CI];     // [n][hp][wp][ci]  ~42 MB
__device__ __half g_wt[(size_t)KTAP * KTAP * CO * CI];      // [tap][co][ci]    ~22 MB

// ---------------------------------------------------------------------------
// Helpers (arch-neutral PTX: mma.sync / ldmatrix / cp.async)
// ---------------------------------------------------------------------------
__device__ __forceinline__ uint32_t smem_u32(const void* p) {
    uint32_t a;
    asm("{ .reg .u64 t; cvta.to.shared.u64 t, %1; cvt.u32.u64 %0, t; }" : "=r"(a) : "l"(p));
    return a;
}
__device__ __forceinline__ uint32_t swz(uint32_t off) {      // SW128: bits[4:6] ^= bits[7:9]
    return off ^ ((off >> 3) & 0x70);
}
__device__ __forceinline__ void cp16(uint32_t dst, const void* src) {
    asm volatile("cp.async.cg.shared.global [%0], [%1], 16;" :: "r"(dst), "l"(src) : "memory");
}
#define CP_COMMIT() asm volatile("cp.async.commit_group;" ::: "memory")
#define CP_WAIT(n)  asm volatile("cp.async.wait_group %0;" :: "n"(n) : "memory")

__device__ __forceinline__ void ldsm4(uint32_t* r, uint32_t addr) {
    asm volatile("ldmatrix.sync.aligned.m8n8.x4.shared.b16 {%0,%1,%2,%3}, [%4];"
                 : "=r"(r[0]), "=r"(r[1]), "=r"(r[2]), "=r"(r[3]) : "r"(addr));
}
__device__ __forceinline__ void ldsm2(uint32_t* r, uint32_t addr) {
    asm volatile("ldmatrix.sync.aligned.m8n8.x2.shared.b16 {%0,%1}, [%2];"
                 : "=r"(r[0]), "=r"(r[1]) : "r"(addr));
}
__device__ __forceinline__ void mma16816(float* d, const uint32_t* a, const uint32_t* b) {
    asm volatile(
        "mma.sync.aligned.m16n8k16.row.col.f32.f16.f16.f32 "
        "{%0,%1,%2,%3}, {%4,%5,%6,%7}, {%8,%9}, {%0,%1,%2,%3};"
        : "+f"(d[0]), "+f"(d[1]), "+f"(d[2]), "+f"(d[3])
        : "r"(a[0]), "r"(a[1]), "r"(a[2]), "r"(a[3]), "r"(b[0]), "r"(b[1]));
}

// ---------------------------------------------------------------------------
// Fused prepass: pad/transpose input + transpose weights (one launch).
// Pad branch writes ONLY valid cells (borders stay zero from static init):
//   - padding-h rows (hp<6 or hp>=62) exit immediately
//   - only wp in [PAD, PAD+56) written
// ---------------------------------------------------------------------------
#define PAD_BLOCKS (N_IMG * HP)          // 1088
#define WT_BLOCKS  (CO * KTAP)           // 3328
#define SROW 57
#define WSROW 258

__global__ void __launch_bounds__(256) prep_kernel(
    const float* __restrict__ x, const float* __restrict__ w)
{
    __shared__ __half s[256 * SROW];
    const int bx  = blockIdx.x;
    const int tid = threadIdx.x;

    if (bx < PAD_BLOCKS) {
        const int n  = bx / HP;
        const int hp = bx % HP;
        const int h  = hp - PAD;
        if (h < 0 || h >= HW) return;          // border rows stay zero
        // Phase 1: coalesced reads along w. Threads = (w:64) x (ci:4).
        const int wq = tid & 63, cq = tid >> 6;
        if (wq < HW) {
            const float* xr = x + ((size_t)(n * CI + cq) * HW + h) * HW + wq;
            #pragma unroll 8
            for (int c0 = 0; c0 < CI; c0 += 4)
                s[(c0 + cq) * SROW + wq] = __float2half(xr[(size_t)c0 * HW * HW]);
        }
        __syncthreads();
        // Phase 2: coalesced half2 stores, valid wp only ([PAD, PAD+56)).
        const int cp2 = tid & 127;
        const int wo  = tid >> 7;
        __half2* dst = (__half2*)(g_xp + ((size_t)(n * HP + hp) * WPAD) * CI) + cp2;
        const __half* s0 = s + (2 * cp2) * SROW;
        const __half* s1 = s + (2 * cp2 + 1) * SROW;
        #pragma unroll
        for (int k = 0; k < HW / 2; ++k) {
            const int ww = wo + 2 * k;         // 0..55
            dst[(size_t)(ww + PAD) * (CI / 2)] = __halves2half2(s0[ww], s1[ww]);
        }
    } else {
        const int idx = bx - PAD_BLOCKS;
        const int co = idx / KTAP;
        const int kr = idx - co * KTAP;
        const float* src = w + ((size_t)co * CI) * (KTAP * KTAP) + kr * KTAP;
        #pragma unroll
        for (int k = 0; k < 13; ++k) {
            const int j  = tid + k * 256;
            const int ci = j / 13;
            const int tp = j - ci * 13;
            s[tp * WSROW + ci] = __float2half(src[(size_t)ci * (KTAP * KTAP) + tp]);
        }
        __syncthreads();
        __half* dst = g_wt + (size_t)(kr * KTAP) * (CO * CI) + (size_t)co * CI + tid;
        #pragma unroll
        for (int tp = 0; tp < 13; ++tp)
            dst[(size_t)tp * (CO * CI)] = s[tp * WSROW + tid];
    }
}

// ---------------------------------------------------------------------------
// Main: implicit-GEMM conv + BN + SiLU via mma.sync (m16n8k16 f16->f32)
// CTA: 128 threads (4 warps 2x2), tile M=128 co x N=112 spatial,
// warp tile 64x56.  3 CTAs/SM, NSTAGE=2, regs<=170, r-skip.
// LPT grid ordering: 704 full-length CTAs first, border CTAs
// (12,12,10,10,8,8 tap-rows) last.  grid = 896 (1-D).   [exact R13 core]
// ---------------------------------------------------------------------------
#define A_BYTES     16384          // 128 rows x 128B
#define B_BYTES     14336          // 112 rows x 128B
#define STAGE_BYTES (A_BYTES + B_BYTES)     // 30720
#define NSTAGE      2
#define SMEM_DYN    (NSTAGE * STAGE_BYTES + 1024)   // 62464

__global__ void __launch_bounds__(128, 3) conv_main_kernel(
    const float* __restrict__ gamma, const float* __restrict__ beta,
    const float* __restrict__ rmean, const float* __restrict__ rvar,
    float* __restrict__ out)
{
    extern __shared__ char smem_raw[];
    const uint32_t base = (smem_u32(smem_raw) + 1023u) & ~1023u;

    const int tid = threadIdx.x;
    const int l   = tid & 31;
    const int wid = tid >> 5;

    // ---- LPT decode: long tiles (ht 3..24) at bids 0..703, border last
    const int idx = blockIdx.x;
    int cob, n, ht;
    if (idx < 704) {
        cob = idx >= 352;
        const int j = idx - cob * 352;
        n  = j / 22;
        ht = 3 + (j - n * 22);                 // 13 tap-rows
    } else {
        const int k = idx - 704;
        cob = k >= 96;
        const int j = k - cob * 96;
        n = j / 6;
        const int b = j - n * 6;               // LPT within border: 12,12,10,10,8,8
        ht = (b == 0) ? 2 : (b == 1) ? 25 : (b == 2) ? 1
           : (b == 3) ? 26 : (b == 4) ? 0 : 27;
    }
    const int h0 = ht * 2;

    // ---- r-skip range
    const int r_lo = max(0, PAD - 1 - h0);
    const int r_hi = min(KTAP - 1, HW + PAD - 1 - h0);
    const int NIT  = 4 * KTAP * (r_hi - r_lo + 1);

    // ---- cp.async geometry: 8x16B per 128B row; 128 thr = 16 rows/pass
    const int c16  = tid & 7;
    const int row0 = tid >> 3;
    const char* a_base = (const char*)g_wt
        + (size_t)(cob * 128 + row0) * (CI * 2) + c16 * 16;
    const uint32_t a_dst0 = swz((uint32_t)(row0 * 128 + c16 * 16));
    const char* b_base = (const char*)g_xp
        + (size_t)(n * HP + h0) * WPAD * (CI * 2) + c16 * 16;
    uint32_t b_off[7];
    #pragma unroll
    for (int i = 0; i < 7; ++i) {
        const int rj = row0 + 16 * i;
        const int jr = (rj >= 56);
        b_off[i] = (uint32_t)(rj + jr * (WPAD - 56)) * (CI * 2);
    }
    const uint32_t b_dst0 = swz((uint32_t)(row0 * 128 + c16 * 16)) + A_BYTES;

    // Producer counters — u32 offsets; start at tap-row r_lo
    uint32_t p_woff = (uint32_t)(r_lo * KTAP) * (CO * CI * 2);
    uint32_t p_xoff = (uint32_t)r_lo * WPAD * (CI * 2);
    int p_kc = 0, p_s = 0, p_ws = 0;

    auto issue = [&]() {
        const uint32_t sb = base + (uint32_t)p_ws * STAGE_BYTES;
        const char* asrc = a_base + p_woff;
        const char* bsrc = b_base + p_xoff;
        #pragma unroll
        for (int i = 0; i < 8; ++i)
            cp16(sb + a_dst0 + i * 2048u, asrc + (size_t)i * 16 * (CI * 2));
        #pragma unroll
        for (int i = 0; i < 7; ++i)
            cp16(sb + b_dst0 + i * 2048u, bsrc + b_off[i]);
        CP_COMMIT();
        p_ws ^= 1;
        p_woff += 128;
        p_xoff += 128;
        if (++p_kc == 4) {
            p_kc = 0;
            p_woff += (uint32_t)(CO * CI * 2) - 512;
            if (++p_s == KTAP) { p_s = 0; p_xoff += (uint32_t)(WPAD - (KTAP - 1)) * (CI * 2) - 512; }
            else               { p_xoff += (uint32_t)(CI * 2) - 512; }
        }
    };

    // ---- MMA fragment geometry (warp grid 2x2, warp tile 64(M) x 56(N))
    const int wm = wid >> 1, wn = wid & 1;
    const int m0 = wm * 64, n0 = wn * 56;
    uint32_t aoff[4], axor[4];
    uint32_t boff[3], bxor[3];
    const uint32_t hi_a = (uint32_t)((l >> 4) << 4);
    const uint32_t hi_b = (uint32_t)(((l >> 3) & 1) << 4);
    #pragma unroll
    for (int mt = 0; mt < 4; ++mt) {
        const int r = m0 + 16 * mt + (l & 15);
        aoff[mt] = (uint32_t)(r * 128);
        axor[mt] = (uint32_t)((r & 7) << 4);
    }
    #pragma unroll
    for (int bt = 0; bt < 3; ++bt) {
        const int r = n0 + 16 * bt + (l & 7) + ((l >> 4) << 3);
        boff[bt] = (uint32_t)(r * 128);
        bxor[bt] = (uint32_t)((r & 7) << 4);
    }
    const int lm = l & 15;
    const int trow = n0 + 48 + (lm & 7);
    const uint32_t toff = (uint32_t)(trow * 128);
    const uint32_t txor = (uint32_t)((trow & 7) << 4);
    const uint32_t thi  = (uint32_t)(((lm >> 3) & 1) << 4);

    float acc[4][7][4];
    #pragma unroll
    for (int i = 0; i < 4; ++i)
        #pragma unroll
        for (int j = 0; j < 7; ++j)
            #pragma unroll
            for (int k = 0; k < 4; ++k) acc[i][j][k] = 0.f;

    auto compute = [&](int stage) {
        const uint32_t ab = base + (uint32_t)stage * STAGE_BYTES;
        const uint32_t bb = ab + A_BYTES;
        #pragma unroll
        for (int kk = 0; kk < 4; ++kk) {
            const uint32_t ka = (uint32_t)kk * 32;
            uint32_t a[4][4], b[3][4], t2[2];
            #pragma unroll
            for (int mt = 0; mt < 4; ++mt)
                ldsm4(a[mt], ab + aoff[mt] + ((ka + hi_a) ^ axor[mt]));
            #pragma unroll
            for (int bt = 0; bt < 3; ++bt)
                ldsm4(b[bt], bb + boff[bt] + ((ka + hi_b) ^ bxor[bt]));
            ldsm2(t2, bb + toff + ((ka + thi) ^ txor));
            #pragma unroll
            for (int bt = 0; bt < 3; ++bt) {
                #pragma unroll
                for (int mt = 0; mt < 4; ++mt) {
                    mma16816(acc[mt][2 * bt],     a[mt], b[bt]);
                    mma16816(acc[mt][2 * bt + 1], a[mt], b[bt] + 2);
                }
            }
            #pragma unroll
            for (int mt = 0; mt < 4; ++mt)
                mma16816(acc[mt][6], a[mt], t2);
        }
    };

    // ---- mainloop: NIT K-stages, 2-stage pipeline, one barrier per iter.
    issue();                        // group 0 -> stage 0
    int rs = 0;
    #pragma unroll 1
    for (int i = 0; i < NIT - 1; ++i) {
        CP_WAIT(0);                 // group i complete (issued 1 iter earlier)
        __syncthreads();
        issue();                    // group i+1 -> stage (i+1)%2
        compute(rs);
        rs ^= 1;
    }
    CP_WAIT(0);
    __syncthreads();
    compute(rs);                    // last iteration

    // ---- epilogue: BN + SiLU, registers -> NCHW fp32 via float2 stores
    const int h = h0 + wn;
    #pragma unroll
    for (int mt = 0; mt < 4; ++mt) {
        #pragma unroll
        for (int hf = 0; hf < 2; ++hf) {
            const int co = cob * 128 + m0 + 16 * mt + 8 * hf + (l >> 2);
            const float sc = gamma[co] * rsqrtf(rvar[co] + 1e-5f);
            const float sh = beta[co] - rmean[co] * sc;
            float* op = out + ((size_t)(n * CO + co) * HW + h) * HW + 2 * (l & 3);
            #pragma unroll
            for (int nt = 0; nt < 7; ++nt) {
                const float y0 = acc[mt][nt][hf * 2 + 0] * sc + sh;
                const float y1 = acc[mt][nt][hf * 2 + 1] * sc + sh;
                float2 v;
                v.x = y0 / (1.f + __expf(-y0));
                v.y = y1 / (1.f + __expf(-y1));
                *(float2*)(op + 8 * nt) = v;
            }
        }
    }
}

// ---------------------------------------------------------------------------
// kernel_launch
// ---------------------------------------------------------------------------
extern "C" void kernel_launch(void* const* d_in, const int* in_sizes, int n_in,
                              void* d_out, int out_size)
{
    const float* x     = (const float*)d_in[0];
    const float* w     = (const float*)d_in[1];
    const float* gamma = (const float*)d_in[2];
    const float* beta  = (const float*)d_in[3];
    const float* rmean = (const float*)d_in[4];
    const float* rvar  = (const float*)d_in[5];
    float* out = (float*)d_out;

    cudaFuncSetAttribute(conv_main_kernel,
                         cudaFuncAttributeMaxDynamicSharedMemorySize, SMEM_DYN);

    prep_kernel<<<PAD_BLOCKS + WT_BLOCKS, 256>>>(x, w);
    conv_main_kernel<<<896, 128, SMEM_DYN>>>(gamma, beta, rmean, rvar, out);
}